// round 9
// baseline (speedup 1.0000x reference)
#include <cuda_runtime.h>
#include <cstdint>

#define N_FEATURES 16
#define N_CLASSES 10
#define N_INTERNAL 1023
#define BLOCK 512
#define GRID 608   // 4 CTAs/SM x 152 SMs
#define N_RECORDS 511

// Dynamic smem: float4 rec[512] only (8 KB)
#define SMEM_BYTES 8192

__global__ __launch_bounds__(BLOCK, 4)
void dtree_kernel(const float* __restrict__ X,
                  const int* __restrict__ tfeat,
                  const float* __restrict__ tthr,
                  const float* __restrict__ tval,
                  float* __restrict__ out,
                  int n)
{
    extern __shared__ char smem_raw[];
    float4* rec_s = reinterpret_cast<float4*>(smem_raw);

    const int tid = threadIdx.x;

    // 2-level records for even-level nodes i (levels 0,2,4,6,8 -> i < 511).
    // feats packed: fI | fL<<4 | fR<<8.
    for (int i = tid; i < N_RECORDS; i += BLOCK) {
        int fI = tfeat[i];
        int fL = tfeat[2 * i + 1];
        int fR = tfeat[2 * i + 2];
        rec_s[i] = make_float4(tthr[i], tthr[2 * i + 1], tthr[2 * i + 2],
                               __int_as_float(fI | (fL << 4) | (fR << 8)));
    }
    __syncthreads();

    const int lane   = tid & 31;
    const int stride = gridDim.x * BLOCK;
    const float2* __restrict__ tv2 = reinterpret_cast<const float2*>(tval);

    for (int i = blockIdx.x * BLOCK + tid; i < n; i += stride) {
        const float4* __restrict__ xr = reinterpret_cast<const float4*>(X + (size_t)i * N_FEATURES);
        float4 a = xr[0], b = xr[1], c = xr[2], d = xr[3];

        int node = 0;
        #pragma unroll
        for (int pair = 0; pair < 5; ++pair) {
            float4 rc = rec_s[node];              // one LDS.128 covers two levels
            const int fp = __float_as_int(rc.w);

            const int f0 = fp & 15;
            float s0 = (f0 & 1) ? a.y : a.x;  float s1 = (f0 & 1) ? a.w : a.z;
            float s2 = (f0 & 1) ? b.y : b.x;  float s3 = (f0 & 1) ? b.w : b.z;
            float s4 = (f0 & 1) ? c.y : c.x;  float s5 = (f0 & 1) ? c.w : c.z;
            float s6 = (f0 & 1) ? d.y : d.x;  float s7 = (f0 & 1) ? d.w : d.z;
            float t0 = (f0 & 2) ? s1 : s0;    float t1 = (f0 & 2) ? s3 : s2;
            float t2 = (f0 & 2) ? s5 : s4;    float t3 = (f0 & 2) ? s7 : s6;
            float u0 = (f0 & 4) ? t1 : t0;    float u1 = (f0 & 4) ? t3 : t2;
            float xv0 = (f0 & 8) ? u1 : u0;
            const bool c0 = (xv0 > rc.x);

            const int   f1   = c0 ? ((fp >> 8) & 15) : ((fp >> 4) & 15);
            const float thr1 = c0 ? rc.z : rc.y;
            float v0 = (f1 & 1) ? a.y : a.x;  float v1 = (f1 & 1) ? a.w : a.z;
            float v2 = (f1 & 1) ? b.y : b.x;  float v3 = (f1 & 1) ? b.w : b.z;
            float v4 = (f1 & 1) ? c.y : c.x;  float v5 = (f1 & 1) ? c.w : c.z;
            float v6 = (f1 & 1) ? d.y : d.x;  float v7 = (f1 & 1) ? d.w : d.z;
            float w0 = (f1 & 2) ? v1 : v0;    float w1 = (f1 & 2) ? v3 : v2;
            float w2 = (f1 & 2) ? v5 : v4;    float w3 = (f1 & 2) ? v7 : v6;
            float y0 = (f1 & 4) ? w1 : w0;    float y1 = (f1 & 4) ? w3 : w2;
            float xv1 = (f1 & 8) ? y1 : y0;
            const bool c1 = (xv1 > thr1);

            node = 4 * node + 3 + (c0 ? 2 : 0) + (c1 ? 1 : 0);
        }

        // Leaf row base (float2 units) into GLOBAL tval — L2-resident (80 KB).
        const int myoff = node * (N_CLASSES / 2);

        // Warp-cooperative: gather rows from L2, write fully-coalesced.
        float2* __restrict__ orow =
            reinterpret_cast<float2*>(out) + (size_t)(i - lane) * (N_CLASSES / 2);
        #pragma unroll
        for (int k = 0; k < 5; ++k) {
            int e  = k * 32 + lane;      // 0..159
            int s  = e / 5;              // sample within warp batch
            int cc = e - s * 5;          // float2 index within row
            int off = __shfl_sync(0xffffffffu, myoff, s);
            orow[e] = __ldg(&tv2[off + cc]);
        }
    }
}

extern "C" void kernel_launch(void* const* d_in, const int* in_sizes, int n_in,
                              void* d_out, int out_size)
{
    const float* X     = (const float*)d_in[0];
    const int*   tfeat = (const int*)  d_in[1];
    const float* tthr  = (const float*)d_in[2];
    // d_in[3]/d_in[4] (left/right): implicit complete binary tree
    const float* tval  = (const float*)d_in[5];
    // d_in[6] (is_leaf): redundant at depth 10

    float* out = (float*)d_out;
    int n = in_sizes[0] / N_FEATURES;

    static bool attr_set = false;
    if (!attr_set) {
        cudaFuncSetAttribute(dtree_kernel,
                             cudaFuncAttributeMaxDynamicSharedMemorySize, SMEM_BYTES);
        attr_set = true;
    }

    int blocks = (n + BLOCK - 1) / BLOCK;
    if (blocks > GRID) blocks = GRID;

    dtree_kernel<<<blocks, BLOCK, SMEM_BYTES>>>(X, tfeat, tthr, tval, out, n);
}

// round 10
// speedup vs baseline: 1.0602x; 1.0602x over previous
#include <cuda_runtime.h>
#include <cstdint>

#define N_FEATURES 16
#define N_CLASSES 10
#define N_INTERNAL 1023
#define BLOCK 512
#define GRID 456   // 3 CTAs/SM x 152 SMs
#define N_RECORDS 511

// Dynamic smem: float4 rec[512] only (8 KB)
#define SMEM_BYTES 8192

__global__ __launch_bounds__(BLOCK, 3)
void dtree_kernel(const float* __restrict__ X,
                  const int* __restrict__ tfeat,
                  const float* __restrict__ tthr,
                  const float* __restrict__ tval,
                  float* __restrict__ out,
                  int n)
{
    extern __shared__ char smem_raw[];
    float4* rec_s = reinterpret_cast<float4*>(smem_raw);

    const int tid = threadIdx.x;

    // 2-level records for even-level nodes i (levels 0,2,4,6,8 -> i < 511).
    // feats packed: fI | fL<<4 | fR<<8.
    for (int i = tid; i < N_RECORDS; i += BLOCK) {
        int fI = tfeat[i];
        int fL = tfeat[2 * i + 1];
        int fR = tfeat[2 * i + 2];
        rec_s[i] = make_float4(tthr[i], tthr[2 * i + 1], tthr[2 * i + 2],
                               __int_as_float(fI | (fL << 4) | (fR << 8)));
    }
    __syncthreads();

    // Levels 0-1 record is the same for every sample: keep it in registers.
    const float4 rc0 = rec_s[0];
    const int    fp0 = __float_as_int(rc0.w);

    const int lane   = tid & 31;
    const int stride = gridDim.x * BLOCK;
    const float2* __restrict__ tv2 = reinterpret_cast<const float2*>(tval);

    for (int i = blockIdx.x * BLOCK + tid; i < n; i += stride) {
        const float4* __restrict__ xr = reinterpret_cast<const float4*>(X + (size_t)i * N_FEATURES);
        float4 a = xr[0], b = xr[1], c = xr[2], d = xr[3];

        int node = 0;
        #pragma unroll
        for (int pair = 0; pair < 5; ++pair) {
            float4 rc;
            int fp;
            if (pair == 0) { rc = rc0; fp = fp0; }          // register-resident, no LDS
            else           { rc = rec_s[node]; fp = __float_as_int(rc.w); }

            const int f0 = fp & 15;
            float s0 = (f0 & 1) ? a.y : a.x;  float s1 = (f0 & 1) ? a.w : a.z;
            float s2 = (f0 & 1) ? b.y : b.x;  float s3 = (f0 & 1) ? b.w : b.z;
            float s4 = (f0 & 1) ? c.y : c.x;  float s5 = (f0 & 1) ? c.w : c.z;
            float s6 = (f0 & 1) ? d.y : d.x;  float s7 = (f0 & 1) ? d.w : d.z;
            float t0 = (f0 & 2) ? s1 : s0;    float t1 = (f0 & 2) ? s3 : s2;
            float t2 = (f0 & 2) ? s5 : s4;    float t3 = (f0 & 2) ? s7 : s6;
            float u0 = (f0 & 4) ? t1 : t0;    float u1 = (f0 & 4) ? t3 : t2;
            float xv0 = (f0 & 8) ? u1 : u0;
            const bool c0 = (xv0 > rc.x);

            const int   f1   = c0 ? ((fp >> 8) & 15) : ((fp >> 4) & 15);
            const float thr1 = c0 ? rc.z : rc.y;
            float v0 = (f1 & 1) ? a.y : a.x;  float v1 = (f1 & 1) ? a.w : a.z;
            float v2 = (f1 & 1) ? b.y : b.x;  float v3 = (f1 & 1) ? b.w : b.z;
            float v4 = (f1 & 1) ? c.y : c.x;  float v5 = (f1 & 1) ? c.w : c.z;
            float v6 = (f1 & 1) ? d.y : d.x;  float v7 = (f1 & 1) ? d.w : d.z;
            float w0 = (f1 & 2) ? v1 : v0;    float w1 = (f1 & 2) ? v3 : v2;
            float w2 = (f1 & 2) ? v5 : v4;    float w3 = (f1 & 2) ? v7 : v6;
            float y0 = (f1 & 4) ? w1 : w0;    float y1 = (f1 & 4) ? w3 : w2;
            float xv1 = (f1 & 8) ? y1 : y0;
            const bool c1 = (xv1 > thr1);

            node = 4 * node + 3 + (c0 ? 2 : 0) + (c1 ? 1 : 0);
        }

        // Leaf row base (float2 units) into GLOBAL tval — L1/L2-resident (80 KB).
        const int myoff = node * (N_CLASSES / 2);

        // Warp-cooperative: gather rows from cache, write fully-coalesced.
        float2* __restrict__ orow =
            reinterpret_cast<float2*>(out) + (size_t)(i - lane) * (N_CLASSES / 2);
        #pragma unroll
        for (int k = 0; k < 5; ++k) {
            int e  = k * 32 + lane;      // 0..159
            int s  = e / 5;              // sample within warp batch
            int cc = e - s * 5;          // float2 index within row
            int off = __shfl_sync(0xffffffffu, myoff, s);
            orow[e] = __ldg(&tv2[off + cc]);
        }
    }
}

extern "C" void kernel_launch(void* const* d_in, const int* in_sizes, int n_in,
                              void* d_out, int out_size)
{
    const float* X     = (const float*)d_in[0];
    const int*   tfeat = (const int*)  d_in[1];
    const float* tthr  = (const float*)d_in[2];
    // d_in[3]/d_in[4] (left/right): implicit complete binary tree
    const float* tval  = (const float*)d_in[5];
    // d_in[6] (is_leaf): redundant at depth 10

    float* out = (float*)d_out;
    int n = in_sizes[0] / N_FEATURES;

    static bool attr_set = false;
    if (!attr_set) {
        cudaFuncSetAttribute(dtree_kernel,
                             cudaFuncAttributeMaxDynamicSharedMemorySize, SMEM_BYTES);
        attr_set = true;
    }

    int blocks = (n + BLOCK - 1) / BLOCK;
    if (blocks > GRID) blocks = GRID;

    dtree_kernel<<<blocks, BLOCK, SMEM_BYTES>>>(X, tfeat, tthr, tval, out, n);
}